// round 8
// baseline (speedup 1.0000x reference)
#include <cuda_runtime.h>
#include <cuda_bf16.h>
#include <cstdint>

#define NV 50000
#define NE_MAX 400000
#define H 128

// Scratch (no cudaMalloc allowed)
__device__ float g_agg[(size_t)NV * H];        // fully written by gather
__device__ int   g_cnt[NV];
__device__ int   g_rowptr[NV + 1];
__device__ int   g_cursor[NV];
__device__ int   g_col[2 * NE_MAX];

// ---------------------------------------------------------------------------
// 1. zero counters (200 KB)
// ---------------------------------------------------------------------------
__global__ void k_zero_cnt() {
    int i = blockIdx.x * blockDim.x + threadIdx.x;
    if (i < NV) g_cnt[i] = 0;
}

// ---------------------------------------------------------------------------
// 2. histogram: every element of edge_idx is a dst exactly once (symmetrized)
// ---------------------------------------------------------------------------
__global__ void k_hist(const int* __restrict__ ei, int total) {
    int i = blockIdx.x * blockDim.x + threadIdx.x;
    int i4 = i * 4;
    if (i4 + 3 < total) {
        int4 v = *reinterpret_cast<const int4*>(ei + i4);
        atomicAdd(&g_cnt[v.x], 1);
        atomicAdd(&g_cnt[v.y], 1);
        atomicAdd(&g_cnt[v.z], 1);
        atomicAdd(&g_cnt[v.w], 1);
    } else {
        for (int j = i4; j < total; j++) atomicAdd(&g_cnt[ei[j]], 1);
    }
}

// ---------------------------------------------------------------------------
// 3. exclusive scan over 50k counts, single CTA of 1024 threads
// ---------------------------------------------------------------------------
#define SCAN_CH 49   // 1024 * 49 = 50176 >= NV
__global__ __launch_bounds__(1024)
void k_scan() {
    __shared__ int ssum[1024];
    int t = threadIdx.x;
    int base = t * SCAN_CH;

    int s = 0;
#pragma unroll 4
    for (int i = 0; i < SCAN_CH; i++) {
        int idx = base + i;
        if (idx < NV) s += g_cnt[idx];
    }
    ssum[t] = s;
    __syncthreads();
    for (int off = 1; off < 1024; off <<= 1) {
        int v = (t >= off) ? ssum[t - off] : 0;
        __syncthreads();
        ssum[t] += v;
        __syncthreads();
    }
    int run = ssum[t] - s;
    for (int i = 0; i < SCAN_CH; i++) {
        int idx = base + i;
        if (idx < NV) {
            int c = g_cnt[idx];
            g_rowptr[idx] = run;
            g_cursor[idx] = run;
            run += c;
        }
    }
    if (t == 1023) g_rowptr[NV] = ssum[1023];
}

// ---------------------------------------------------------------------------
// 4. fill: one thread per DIRECTED edge -> exactly 1 atomic per thread
// ---------------------------------------------------------------------------
__global__ void k_fill(const int* __restrict__ ei, int nE) {
    int t = blockIdx.x * blockDim.x + threadIdx.x;
    if (t >= 2 * nE) return;
    int src, dst;
    if (t < nE) { src = ei[t]; dst = ei[nE + t]; }
    else        { int e = t - nE; src = ei[nE + e]; dst = ei[e]; }
    int p = atomicAdd(&g_cursor[dst], 1);
    g_col[p] = src;
}

// ---------------------------------------------------------------------------
// 5. gather v3 (FIXED): warp per vertex, lane owns float4 chunk `lane`
//    (32 x 16B = full 512B row). Neighbor loop 4-way unrolled -> 4
//    independent LDG.128 in flight per thread. No shfl, no atomics.
// ---------------------------------------------------------------------------
__global__ __launch_bounds__(256)
void k_gather(const float* __restrict__ x) {
    int gt   = blockIdx.x * blockDim.x + threadIdx.x;
    int v    = gt >> 5;         // vertex (warp per vertex)
    int lane = gt & 31;         // float4 chunk 0..31
    if (v >= NV) return;

    int beg = g_rowptr[v];
    int end = g_rowptr[v + 1];

    float4 acc = make_float4(0.f, 0.f, 0.f, 0.f);
    int j = beg;
    for (; j + 4 <= end; j += 4) {
        int u0 = __ldg(g_col + j + 0);
        int u1 = __ldg(g_col + j + 1);
        int u2 = __ldg(g_col + j + 2);
        int u3 = __ldg(g_col + j + 3);
        float4 t0 = __ldg(reinterpret_cast<const float4*>(x + (size_t)u0 * H) + lane);
        float4 t1 = __ldg(reinterpret_cast<const float4*>(x + (size_t)u1 * H) + lane);
        float4 t2 = __ldg(reinterpret_cast<const float4*>(x + (size_t)u2 * H) + lane);
        float4 t3 = __ldg(reinterpret_cast<const float4*>(x + (size_t)u3 * H) + lane);
        acc.x += t0.x + t1.x + t2.x + t3.x;
        acc.y += t0.y + t1.y + t2.y + t3.y;
        acc.z += t0.z + t1.z + t2.z + t3.z;
        acc.w += t0.w + t1.w + t2.w + t3.w;
    }
    for (; j < end; j++) {
        int u = __ldg(g_col + j);
        float4 t = __ldg(reinterpret_cast<const float4*>(x + (size_t)u * H) + lane);
        acc.x += t.x; acc.y += t.y; acc.z += t.z; acc.w += t.w;
    }
    reinterpret_cast<float4*>(g_agg + (size_t)v * H)[lane] = acc;
}

// ---------------------------------------------------------------------------
// 6. HMMA GEMM: out = [agg | deg*x] @ W^T, bf16 hi/lo split (fp32 accum)
// ---------------------------------------------------------------------------
#define BK 32
#define PITCH 40

__device__ __forceinline__ uint32_t pack_bf2(float a, float b) {
    __nv_bfloat162 h = __floats2bfloat162_rn(a, b);
    return *reinterpret_cast<uint32_t*>(&h);
}

__device__ __forceinline__ void mma_16816(float* c, const uint32_t* a,
                                          uint32_t b0, uint32_t b1) {
    asm volatile(
        "mma.sync.aligned.m16n8k16.row.col.f32.bf16.bf16.f32 "
        "{%0,%1,%2,%3}, {%4,%5,%6,%7}, {%8,%9}, {%0,%1,%2,%3};"
        : "+f"(c[0]), "+f"(c[1]), "+f"(c[2]), "+f"(c[3])
        : "r"(a[0]), "r"(a[1]), "r"(a[2]), "r"(a[3]), "r"(b0), "r"(b1));
}

__global__ __launch_bounds__(256)
void k_gemm(const float* __restrict__ x, const float* __restrict__ W,
            float* __restrict__ out) {
    __shared__ __align__(16) __nv_bfloat16 Ahi[128][PITCH];
    __shared__ __align__(16) __nv_bfloat16 Alo[128][PITCH];
    __shared__ __align__(16) __nv_bfloat16 Bhi[128][PITCH];
    __shared__ __align__(16) __nv_bfloat16 Blo[128][PITCH];

    const int tid    = threadIdx.x;
    const int wid    = tid >> 5;
    const int lane   = tid & 31;
    const int grp    = lane >> 2;
    const int tig    = lane & 3;
    const int warp_m = wid & 3;
    const int warp_n = wid >> 2;
    const int row0   = blockIdx.x * 128;

    float acc[2][8][4];
#pragma unroll
    for (int mi = 0; mi < 2; mi++)
#pragma unroll
        for (int ni = 0; ni < 8; ni++)
#pragma unroll
            for (int q = 0; q < 4; q++) acc[mi][ni][q] = 0.0f;

    for (int kt = 0; kt < 8; kt++) {
        __syncthreads();
#pragma unroll
        for (int p = 0; p < 4; p++) {
            int idx  = p * 256 + tid;
            int row  = idx >> 3;
            int colq = idx & 7;
            int grow = row0 + row;
            float4 v = make_float4(0.f, 0.f, 0.f, 0.f);
            if (grow < NV) {
                if (kt < 4) {
                    v = *reinterpret_cast<const float4*>(
                        g_agg + (size_t)grow * H + kt * BK + colq * 4);
                } else {
                    v = *reinterpret_cast<const float4*>(
                        x + (size_t)grow * H + (kt - 4) * BK + colq * 4);
                    float dg = (float)(g_rowptr[grow + 1] - g_rowptr[grow]);
                    v.x *= dg; v.y *= dg; v.z *= dg; v.w *= dg;
                }
            }
            float hx = __bfloat162float(__float2bfloat16(v.x));
            float hy = __bfloat162float(__float2bfloat16(v.y));
            float hz = __bfloat162float(__float2bfloat16(v.z));
            float hw = __bfloat162float(__float2bfloat16(v.w));
            uint2 hp = make_uint2(pack_bf2(hx, hy), pack_bf2(hz, hw));
            uint2 lp = make_uint2(pack_bf2(v.x - hx, v.y - hy),
                                  pack_bf2(v.z - hz, v.w - hw));
            *reinterpret_cast<uint2*>(&Ahi[row][colq * 4]) = hp;
            *reinterpret_cast<uint2*>(&Alo[row][colq * 4]) = lp;
        }
#pragma unroll
        for (int p = 0; p < 4; p++) {
            int idx  = p * 256 + tid;
            int n    = idx >> 3;
            int colq = idx & 7;
            float4 v = *reinterpret_cast<const float4*>(
                W + (size_t)n * (2 * H) + kt * BK + colq * 4);
            float hx = __bfloat162float(__float2bfloat16(v.x));
            float hy = __bfloat162float(__float2bfloat16(v.y));
            float hz = __bfloat162float(__float2bfloat16(v.z));
            float hw = __bfloat162float(__float2bfloat16(v.w));
            uint2 hp = make_uint2(pack_bf2(hx, hy), pack_bf2(hz, hw));
            uint2 lp = make_uint2(pack_bf2(v.x - hx, v.y - hy),
                                  pack_bf2(v.z - hz, v.w - hw));
            *reinterpret_cast<uint2*>(&Bhi[n][colq * 4]) = hp;
            *reinterpret_cast<uint2*>(&Blo[n][colq * 4]) = lp;
        }
        __syncthreads();

#pragma unroll
        for (int ks = 0; ks < 2; ks++) {
            int kb = ks * 16 + tig * 2;
            uint32_t ah[2][4], al[2][4];
#pragma unroll
            for (int mi = 0; mi < 2; mi++) {
                int r = warp_m * 32 + mi * 16 + grp;
                ah[mi][0] = *reinterpret_cast<const uint32_t*>(&Ahi[r][kb]);
                ah[mi][1] = *reinterpret_cast<const uint32_t*>(&Ahi[r + 8][kb]);
                ah[mi][2] = *reinterpret_cast<const uint32_t*>(&Ahi[r][kb + 8]);
                ah[mi][3] = *reinterpret_cast<const uint32_t*>(&Ahi[r + 8][kb + 8]);
                al[mi][0] = *reinterpret_cast<const uint32_t*>(&Alo[r][kb]);
                al[mi][1] = *reinterpret_cast<const uint32_t*>(&Alo[r + 8][kb]);
                al[mi][2] = *reinterpret_cast<const uint32_t*>(&Alo[r][kb + 8]);
                al[mi][3] = *reinterpret_cast<const uint32_t*>(&Alo[r + 8][kb + 8]);
            }
#pragma unroll
            for (int ni = 0; ni < 8; ni++) {
                int n = warp_n * 64 + ni * 8 + grp;
                uint32_t bh0 = *reinterpret_cast<const uint32_t*>(&Bhi[n][kb]);
                uint32_t bh1 = *reinterpret_cast<const uint32_t*>(&Bhi[n][kb + 8]);
                uint32_t bl0 = *reinterpret_cast<const uint32_t*>(&Blo[n][kb]);
                uint32_t bl1 = *reinterpret_cast<const uint32_t*>(&Blo[n][kb + 8]);
#pragma unroll
                for (int mi = 0; mi < 2; mi++) {
                    mma_16816(acc[mi][ni], ah[mi], bh0, bh1);
                    mma_16816(acc[mi][ni], ah[mi], bl0, bl1);
                    mma_16816(acc[mi][ni], al[mi], bh0, bh1);
                }
            }
        }
    }

#pragma unroll
    for (int mi = 0; mi < 2; mi++) {
        int r0 = row0 + warp_m * 32 + mi * 16 + grp;
#pragma unroll
        for (int ni = 0; ni < 8; ni++) {
            int col = warp_n * 64 + ni * 8 + tig * 2;
            if (r0 < NV)
                *reinterpret_cast<float2*>(out + (size_t)r0 * H + col) =
                    make_float2(acc[mi][ni][0], acc[mi][ni][1]);
            if (r0 + 8 < NV)
                *reinterpret_cast<float2*>(out + (size_t)(r0 + 8) * H + col) =
                    make_float2(acc[mi][ni][2], acc[mi][ni][3]);
        }
    }
}

// ---------------------------------------------------------------------------
extern "C" void kernel_launch(void* const* d_in, const int* in_sizes, int n_in,
                              void* d_out, int out_size) {
    const float* x  = (const float*)d_in[0];   // [NV, 128] f32
    const float* W  = (const float*)d_in[1];   // [128, 256] f32
    const int*   ei = (const int*)d_in[2];     // [2, E] i32
    float* out = (float*)d_out;                // [NV, 128] f32

    int nE    = in_sizes[2] / 2;
    int total = in_sizes[2];

    k_zero_cnt<<<(NV + 255) / 256, 256>>>();
    k_hist<<<(total / 4 + 255) / 256, 256>>>(ei, total);
    k_scan<<<1, 1024>>>();
    k_fill<<<(2 * nE + 255) / 256, 256>>>(ei, nE);
    k_gather<<<(NV * 32 + 255) / 256, 256>>>(x);
    k_gemm<<<(NV + 127) / 128, 256>>>(x, W, out);

    (void)n_in; (void)out_size;
}

// round 11
// speedup vs baseline: 1.8350x; 1.8350x over previous
#include <cuda_runtime.h>
#include <cuda_bf16.h>
#include <cstdint>

#define NV 50000
#define H 128

// Scratch (no cudaMalloc allowed) — same footprint class as proven R4 kernel
__device__ float g_y1[(size_t)NV * H];   // 25.6 MB, x @ W1^T
__device__ int   g_cnt[NV];              // degree

// ---------------------------------------------------------------------------
// 1. zero degree counters
// ---------------------------------------------------------------------------
__global__ void k_zero_cnt() {
    int i = blockIdx.x * blockDim.x + threadIdx.x;
    if (i < NV) g_cnt[i] = 0;
}

// ---------------------------------------------------------------------------
// 2. degree histogram: every element of edge_idx is a dst exactly once
// ---------------------------------------------------------------------------
__global__ void k_hist(const int* __restrict__ ei, int total) {
    int i = blockIdx.x * blockDim.x + threadIdx.x;
    int i4 = i * 4;
    if (i4 + 3 < total) {
        int4 v = *reinterpret_cast<const int4*>(ei + i4);
        atomicAdd(&g_cnt[v.x], 1);
        atomicAdd(&g_cnt[v.y], 1);
        atomicAdd(&g_cnt[v.z], 1);
        atomicAdd(&g_cnt[v.w], 1);
    } else {
        for (int j = i4; j < total; j++) atomicAdd(&g_cnt[ei[j]], 1);
    }
}

// ---------------------------------------------------------------------------
// 3. HMMA GEMM (R4-proven structure): Y[M, 256] = x[M,128] @ Wcat^T
//    Wcat[n][k] = (n < 128) ? W[n][k] : W[n-128][128+k]
//              == W[(n&127)*256 + ncol0 + k]  with ncol0 = (n>=128)*128
//    grid.y == 0 -> columns [0,128)   -> g_y1
//    grid.y == 1 -> columns [128,256) -> out, scaled by deg(row)
//    bf16 hi/lo split in-kernel: acc += Ahi*Bhi + Ahi*Blo + Alo*Bhi
// ---------------------------------------------------------------------------
#define BK 32
#define PITCH 40

__device__ __forceinline__ uint32_t pack_bf2(float a, float b) {
    __nv_bfloat162 h = __floats2bfloat162_rn(a, b);
    return *reinterpret_cast<uint32_t*>(&h);
}

__device__ __forceinline__ void mma_16816(float* c, const uint32_t* a,
                                          uint32_t b0, uint32_t b1) {
    asm volatile(
        "mma.sync.aligned.m16n8k16.row.col.f32.bf16.bf16.f32 "
        "{%0,%1,%2,%3}, {%4,%5,%6,%7}, {%8,%9}, {%0,%1,%2,%3};"
        : "+f"(c[0]), "+f"(c[1]), "+f"(c[2]), "+f"(c[3])
        : "r"(a[0]), "r"(a[1]), "r"(a[2]), "r"(a[3]), "r"(b0), "r"(b1));
}

__global__ __launch_bounds__(256)
void k_gemm(const float* __restrict__ x, const float* __restrict__ W,
            float* __restrict__ out) {
    __shared__ __align__(16) __nv_bfloat16 Ahi[128][PITCH];
    __shared__ __align__(16) __nv_bfloat16 Alo[128][PITCH];
    __shared__ __align__(16) __nv_bfloat16 Bhi[128][PITCH];
    __shared__ __align__(16) __nv_bfloat16 Blo[128][PITCH];

    const int tid    = threadIdx.x;
    const int wid    = tid >> 5;
    const int lane   = tid & 31;
    const int grp    = lane >> 2;
    const int tig    = lane & 3;
    const int warp_m = wid & 3;
    const int warp_n = wid >> 2;
    const int row0   = blockIdx.x * 128;
    const int ncol0  = blockIdx.y * 128;      // 0 or 128 (k-offset into W rows)

    float acc[2][8][4];
#pragma unroll
    for (int mi = 0; mi < 2; mi++)
#pragma unroll
        for (int ni = 0; ni < 8; ni++)
#pragma unroll
            for (int q = 0; q < 4; q++) acc[mi][ni][q] = 0.0f;

    for (int kt = 0; kt < 4; kt++) {          // K = 128 in chunks of 32
        __syncthreads();
        // ---- A tile: x[row0+row][kt*32 + 0..31], fp32 -> hi/lo ----
#pragma unroll
        for (int p = 0; p < 4; p++) {
            int idx  = p * 256 + tid;          // 0..1023
            int row  = idx >> 3;               // 0..127
            int colq = idx & 7;                // float4 group 0..7
            int grow = row0 + row;
            float4 v = make_float4(0.f, 0.f, 0.f, 0.f);
            if (grow < NV)
                v = *reinterpret_cast<const float4*>(
                    x + (size_t)grow * H + kt * BK + colq * 4);
            float hx = __bfloat162float(__float2bfloat16(v.x));
            float hy = __bfloat162float(__float2bfloat16(v.y));
            float hz = __bfloat162float(__float2bfloat16(v.z));
            float hw = __bfloat162float(__float2bfloat16(v.w));
            uint2 hp = make_uint2(pack_bf2(hx, hy), pack_bf2(hz, hw));
            uint2 lp = make_uint2(pack_bf2(v.x - hx, v.y - hy),
                                  pack_bf2(v.z - hz, v.w - hw));
            *reinterpret_cast<uint2*>(&Ahi[row][colq * 4]) = hp;
            *reinterpret_cast<uint2*>(&Alo[row][colq * 4]) = lp;
        }
        // ---- B tile: Bs[n][k] = W[n*256 + ncol0 + kt*32 + k] ----
#pragma unroll
        for (int p = 0; p < 4; p++) {
            int idx  = p * 256 + tid;
            int n    = idx >> 3;
            int colq = idx & 7;
            float4 v = *reinterpret_cast<const float4*>(
                W + (size_t)n * (2 * H) + ncol0 + kt * BK + colq * 4);
            float hx = __bfloat162float(__float2bfloat16(v.x));
            float hy = __bfloat162float(__float2bfloat16(v.y));
            float hz = __bfloat162float(__float2bfloat16(v.z));
            float hw = __bfloat162float(__float2bfloat16(v.w));
            uint2 hp = make_uint2(pack_bf2(hx, hy), pack_bf2(hz, hw));
            uint2 lp = make_uint2(pack_bf2(v.x - hx, v.y - hy),
                                  pack_bf2(v.z - hz, v.w - hw));
            *reinterpret_cast<uint2*>(&Bhi[n][colq * 4]) = hp;
            *reinterpret_cast<uint2*>(&Blo[n][colq * 4]) = lp;
        }
        __syncthreads();

#pragma unroll
        for (int ks = 0; ks < 2; ks++) {
            int kb = ks * 16 + tig * 2;
            uint32_t ah[2][4], al[2][4];
#pragma unroll
            for (int mi = 0; mi < 2; mi++) {
                int r = warp_m * 32 + mi * 16 + grp;
                ah[mi][0] = *reinterpret_cast<const uint32_t*>(&Ahi[r][kb]);
                ah[mi][1] = *reinterpret_cast<const uint32_t*>(&Ahi[r + 8][kb]);
                ah[mi][2] = *reinterpret_cast<const uint32_t*>(&Ahi[r][kb + 8]);
                ah[mi][3] = *reinterpret_cast<const uint32_t*>(&Ahi[r + 8][kb + 8]);
                al[mi][0] = *reinterpret_cast<const uint32_t*>(&Alo[r][kb]);
                al[mi][1] = *reinterpret_cast<const uint32_t*>(&Alo[r + 8][kb]);
                al[mi][2] = *reinterpret_cast<const uint32_t*>(&Alo[r][kb + 8]);
                al[mi][3] = *reinterpret_cast<const uint32_t*>(&Alo[r + 8][kb + 8]);
            }
#pragma unroll
            for (int ni = 0; ni < 8; ni++) {
                int n = warp_n * 64 + ni * 8 + grp;
                uint32_t bh0 = *reinterpret_cast<const uint32_t*>(&Bhi[n][kb]);
                uint32_t bh1 = *reinterpret_cast<const uint32_t*>(&Bhi[n][kb + 8]);
                uint32_t bl0 = *reinterpret_cast<const uint32_t*>(&Blo[n][kb]);
                uint32_t bl1 = *reinterpret_cast<const uint32_t*>(&Blo[n][kb + 8]);
#pragma unroll
                for (int mi = 0; mi < 2; mi++) {
                    mma_16816(acc[mi][ni], ah[mi], bh0, bh1);
                    mma_16816(acc[mi][ni], ah[mi], bl0, bl1);
                    mma_16816(acc[mi][ni], al[mi], bh0, bh1);
                }
            }
        }
    }

    // ---- epilogue: half 0 -> g_y1, half 1 -> out (scaled by deg) ----
    const bool to_out = (blockIdx.y == 1);
    float* dst = to_out ? out : g_y1;
#pragma unroll
    for (int mi = 0; mi < 2; mi++) {
        int r0 = row0 + warp_m * 32 + mi * 16 + grp;
        float dg0 = 1.0f, dg1 = 1.0f;
        if (to_out) {
            if (r0 < NV)     dg0 = (float)g_cnt[r0];
            if (r0 + 8 < NV) dg1 = (float)g_cnt[r0 + 8];
        }
#pragma unroll
        for (int ni = 0; ni < 8; ni++) {
            int col = warp_n * 64 + ni * 8 + tig * 2;
            if (r0 < NV)
                *reinterpret_cast<float2*>(dst + (size_t)r0 * H + col) =
                    make_float2(acc[mi][ni][0] * dg0, acc[mi][ni][1] * dg0);
            if (r0 + 8 < NV)
                *reinterpret_cast<float2*>(dst + (size_t)(r0 + 8) * H + col) =
                    make_float2(acc[mi][ni][2] * dg1, acc[mi][ni][3] * dg1);
        }
    }
}

// ---------------------------------------------------------------------------
// 4. scatter (proven R4 structure): warp per directed edge,
//    out[dst] += y1[src] via red.global.add.v4.f32 (no deg atomic needed)
// ---------------------------------------------------------------------------
__global__ __launch_bounds__(256)
void k_scatter(const int* __restrict__ ei, int nE, float* __restrict__ out) {
    int gw   = (int)(((unsigned)blockIdx.x * blockDim.x + threadIdx.x) >> 5);
    int lane = threadIdx.x & 31;
    if (gw >= 2 * nE) return;

    int s, d;
    if (gw < nE) { s = ei[gw];      d = ei[nE + gw]; }
    else         { int e = gw - nE; d = ei[e]; s = ei[nE + e]; }

    float4 v = reinterpret_cast<const float4*>(g_y1 + (size_t)s * H)[lane];
    float4* o = reinterpret_cast<float4*>(out + (size_t)d * H) + lane;
    asm volatile("red.global.add.v4.f32 [%0], {%1, %2, %3, %4};"
                 :: "l"(o), "f"(v.x), "f"(v.y), "f"(v.z), "f"(v.w)
                 : "memory");
}

// ---------------------------------------------------------------------------
extern "C" void kernel_launch(void* const* d_in, const int* in_sizes, int n_in,
                              void* d_out, int out_size) {
    const float* x  = (const float*)d_in[0];   // [NV, 128] f32
    const float* W  = (const float*)d_in[1];   // [128, 256] f32
    const int*   ei = (const int*)d_in[2];     // [2, E] i32
    float* out = (float*)d_out;                // [NV, 128] f32

    int nE    = in_sizes[2] / 2;
    int total = in_sizes[2];

    k_zero_cnt<<<(NV + 255) / 256, 256>>>();
    k_hist<<<(total / 4 + 255) / 256, 256>>>(ei, total);

    dim3 ggrid((NV + 127) / 128, 2);
    k_gemm<<<ggrid, 256>>>(x, W, out);

    k_scatter<<<(2 * nE * 32 + 255) / 256, 256>>>(ei, nE, out);

    (void)n_in; (void)out_size;
}

// round 12
// speedup vs baseline: 2.0476x; 1.1158x over previous
#include <cuda_runtime.h>
#include <cuda_bf16.h>
#include <cstdint>

#define NV 50000
#define H 128

// Scratch (no cudaMalloc allowed)
__device__ float g_y1[(size_t)NV * H];   // 25.6 MB, x @ W1^T
__device__ int   g_cnt[NV];              // degree

// ---------------------------------------------------------------------------
// 1. zero degree counters
// ---------------------------------------------------------------------------
__global__ void k_zero_cnt() {
    int i = blockIdx.x * blockDim.x + threadIdx.x;
    if (i < NV) g_cnt[i] = 0;
}

// ---------------------------------------------------------------------------
// 2. degree histogram: every element of edge_idx is a dst exactly once
// ---------------------------------------------------------------------------
__global__ void k_hist(const int* __restrict__ ei, int total) {
    int i = blockIdx.x * blockDim.x + threadIdx.x;
    int i4 = i * 4;
    if (i4 + 3 < total) {
        int4 v = *reinterpret_cast<const int4*>(ei + i4);
        atomicAdd(&g_cnt[v.x], 1);
        atomicAdd(&g_cnt[v.y], 1);
        atomicAdd(&g_cnt[v.z], 1);
        atomicAdd(&g_cnt[v.w], 1);
    } else {
        for (int j = i4; j < total; j++) atomicAdd(&g_cnt[ei[j]], 1);
    }
}

// ---------------------------------------------------------------------------
// 3. HMMA GEMM v2: Y[M, 256] = x[M,128] @ Wcat^T
//    grid.y == 0 -> cols [0,128)   -> g_y1
//    grid.y == 1 -> cols [128,256) -> out, scaled by deg(row)
//    bf16 hi/lo split (hi = truncation via PRMT), fragments via ldmatrix.
// ---------------------------------------------------------------------------
#define BK 32
#define PITCH 40   // bf16 elems per smem row (80 B): rows land on distinct banks

__device__ __forceinline__ void mma_16816(float* c, const uint32_t* a,
                                          uint32_t b0, uint32_t b1) {
    asm volatile(
        "mma.sync.aligned.m16n8k16.row.col.f32.bf16.bf16.f32 "
        "{%0,%1,%2,%3}, {%4,%5,%6,%7}, {%8,%9}, {%0,%1,%2,%3};"
        : "+f"(c[0]), "+f"(c[1]), "+f"(c[2]), "+f"(c[3])
        : "r"(a[0]), "r"(a[1]), "r"(a[2]), "r"(a[3]), "r"(b0), "r"(b1));
}

#define LDSM_X4(r0, r1, r2, r3, addr) \
    asm volatile("ldmatrix.sync.aligned.m8n8.x4.shared.b16 {%0,%1,%2,%3}, [%4];" \
                 : "=r"(r0), "=r"(r1), "=r"(r2), "=r"(r3) : "r"(addr))

__global__ __launch_bounds__(256)
void k_gemm(const float* __restrict__ x, const float* __restrict__ W,
            float* __restrict__ out) {
    __shared__ __align__(16) __nv_bfloat16 Ahi[128][PITCH];
    __shared__ __align__(16) __nv_bfloat16 Alo[128][PITCH];
    __shared__ __align__(16) __nv_bfloat16 Bhi[128][PITCH];
    __shared__ __align__(16) __nv_bfloat16 Blo[128][PITCH];

    const int tid    = threadIdx.x;
    const int wid    = tid >> 5;
    const int lane   = tid & 31;
    const int grp    = lane >> 2;
    const int tig    = lane & 3;
    const int warp_m = wid & 3;
    const int warp_n = wid >> 2;
    const int row0   = blockIdx.x * 128;
    const int ncol0  = blockIdx.y * 128;      // k-offset into W rows

    const uint32_t sAhi = (uint32_t)__cvta_generic_to_shared(&Ahi[0][0]);
    const uint32_t sAlo = (uint32_t)__cvta_generic_to_shared(&Alo[0][0]);
    const uint32_t sBhi = (uint32_t)__cvta_generic_to_shared(&Bhi[0][0]);
    const uint32_t sBlo = (uint32_t)__cvta_generic_to_shared(&Blo[0][0]);

    // ldmatrix lane->address maps (byte offsets; 2 B per elem)
    // A x4: m0 rows 0-7 k0, m1 rows 8-15 k0, m2 rows 0-7 k8, m3 rows 8-15 k8
    const int a_row16 = (lane & 7) + ((lane >> 3) & 1) * 8;
    const int a_k8    = ((lane >> 4) & 1) * 8;
    const uint32_t aoff = (uint32_t)(((warp_m * 32 + a_row16) * PITCH + a_k8) * 2);
    // B x4 (pair of 8-col groups): m0 n0-7 k0, m1 n0-7 k8, m2 n8-15 k0, m3 n8-15 k8
    const int b_row16 = (lane & 7) + ((lane >> 4) & 1) * 8;
    const int b_k8    = ((lane >> 3) & 1) * 8;
    const uint32_t boff = (uint32_t)(((warp_n * 64 + b_row16) * PITCH + b_k8) * 2);

    float acc[2][8][4];
#pragma unroll
    for (int mi = 0; mi < 2; mi++)
#pragma unroll
        for (int ni = 0; ni < 8; ni++)
#pragma unroll
            for (int q = 0; q < 4; q++) acc[mi][ni][q] = 0.0f;

    for (int kt = 0; kt < 4; kt++) {          // K = 128 in chunks of 32
        __syncthreads();
        // ---- A tile: x[row0+row][kt*32 + 0..31], fp32 -> hi(trunc)/lo ----
#pragma unroll
        for (int p = 0; p < 4; p++) {
            int idx  = p * 256 + tid;          // 0..1023
            int row  = idx >> 3;               // 0..127
            int colq = idx & 7;                // float4 group 0..7
            int grow = row0 + row;
            float4 v = make_float4(0.f, 0.f, 0.f, 0.f);
            if (grow < NV)
                v = *reinterpret_cast<const float4*>(
                    x + (size_t)grow * H + kt * BK + colq * 4);
            uint32_t bx = __float_as_uint(v.x), by = __float_as_uint(v.y);
            uint32_t bz = __float_as_uint(v.z), bw = __float_as_uint(v.w);
            uint32_t hp0 = __byte_perm(bx, by, 0x7632);
            uint32_t hp1 = __byte_perm(bz, bw, 0x7632);
            float lx = v.x - __uint_as_float(bx & 0xFFFF0000u);
            float ly = v.y - __uint_as_float(by & 0xFFFF0000u);
            float lz = v.z - __uint_as_float(bz & 0xFFFF0000u);
            float lw = v.w - __uint_as_float(bw & 0xFFFF0000u);
            __nv_bfloat162 l0 = __floats2bfloat162_rn(lx, ly);
            __nv_bfloat162 l1 = __floats2bfloat162_rn(lz, lw);
            *reinterpret_cast<uint2*>(&Ahi[row][colq * 4]) = make_uint2(hp0, hp1);
            *reinterpret_cast<uint2*>(&Alo[row][colq * 4]) =
                make_uint2(*reinterpret_cast<uint32_t*>(&l0),
                           *reinterpret_cast<uint32_t*>(&l1));
        }
        // ---- B tile: Bs[n][k] = W[n*256 + ncol0 + kt*32 + k] ----
#pragma unroll
        for (int p = 0; p < 4; p++) {
            int idx  = p * 256 + tid;
            int n    = idx >> 3;
            int colq = idx & 7;
            float4 v = *reinterpret_cast<const float4*>(
                W + (size_t)n * (2 * H) + ncol0 + kt * BK + colq * 4);
            uint32_t bx = __float_as_uint(v.x), by = __float_as_uint(v.y);
            uint32_t bz = __float_as_uint(v.z), bw = __float_as_uint(v.w);
            uint32_t hp0 = __byte_perm(bx, by, 0x7632);
            uint32_t hp1 = __byte_perm(bz, bw, 0x7632);
            float lx = v.x - __uint_as_float(bx & 0xFFFF0000u);
            float ly = v.y - __uint_as_float(by & 0xFFFF0000u);
            float lz = v.z - __uint_as_float(bz & 0xFFFF0000u);
            float lw = v.w - __uint_as_float(bw & 0xFFFF0000u);
            __nv_bfloat162 l0 = __floats2bfloat162_rn(lx, ly);
            __nv_bfloat162 l1 = __floats2bfloat162_rn(lz, lw);
            *reinterpret_cast<uint2*>(&Bhi[n][colq * 4]) = make_uint2(hp0, hp1);
            *reinterpret_cast<uint2*>(&Blo[n][colq * 4]) =
                make_uint2(*reinterpret_cast<uint32_t*>(&l0),
                           *reinterpret_cast<uint32_t*>(&l1));
        }
        __syncthreads();

#pragma unroll
        for (int ks = 0; ks < 2; ks++) {
            const uint32_t koff = (uint32_t)(ks * 16 * 2);   // bytes
            uint32_t ah[2][4], al[2][4];
#pragma unroll
            for (int mi = 0; mi < 2; mi++) {
                uint32_t ao = aoff + (uint32_t)(mi * 16 * PITCH * 2) + koff;
                LDSM_X4(ah[mi][0], ah[mi][1], ah[mi][2], ah[mi][3], sAhi + ao);
                LDSM_X4(al[mi][0], al[mi][1], al[mi][2], al[mi][3], sAlo + ao);
            }
            uint32_t bh[8][2], bl[8][2];
#pragma unroll
            for (int pr = 0; pr < 4; pr++) {
                uint32_t bo = boff + (uint32_t)(pr * 16 * PITCH * 2) + koff;
                LDSM_X4(bh[pr * 2][0], bh[pr * 2][1],
                        bh[pr * 2 + 1][0], bh[pr * 2 + 1][1], sBhi + bo);
                LDSM_X4(bl[pr * 2][0], bl[pr * 2][1],
                        bl[pr * 2 + 1][0], bl[pr * 2 + 1][1], sBlo + bo);
            }
#pragma unroll
            for (int ni = 0; ni < 8; ni++) {
#pragma unroll
                for (int mi = 0; mi < 2; mi++) {
                    mma_16816(acc[mi][ni], ah[mi], bh[ni][0], bh[ni][1]);
                    mma_16816(acc[mi][ni], ah[mi], bl[ni][0], bl[ni][1]);
                    mma_16816(acc[mi][ni], al[mi], bh[ni][0], bh[ni][1]);
                }
            }
        }
    }

    // ---- epilogue: half 0 -> g_y1, half 1 -> out (scaled by deg) ----
    const bool to_out = (blockIdx.y == 1);
    float* dst = to_out ? out : g_y1;
#pragma unroll
    for (int mi = 0; mi < 2; mi++) {
        int r0 = row0 + warp_m * 32 + mi * 16 + grp;
        float dg0 = 1.0f, dg1 = 1.0f;
        if (to_out) {
            if (r0 < NV)     dg0 = (float)g_cnt[r0];
            if (r0 + 8 < NV) dg1 = (float)g_cnt[r0 + 8];
        }
#pragma unroll
        for (int ni = 0; ni < 8; ni++) {
            int col = warp_n * 64 + ni * 8 + tig * 2;
            if (r0 < NV)
                *reinterpret_cast<float2*>(dst + (size_t)r0 * H + col) =
                    make_float2(acc[mi][ni][0] * dg0, acc[mi][ni][1] * dg0);
            if (r0 + 8 < NV)
                *reinterpret_cast<float2*>(dst + (size_t)(r0 + 8) * H + col) =
                    make_float2(acc[mi][ni][2] * dg1, acc[mi][ni][3] * dg1);
        }
    }
}

// ---------------------------------------------------------------------------
// 4. scatter (proven; at REDG issue floor): warp per directed edge,
//    out[dst] += y1[src] via red.global.add.v4.f32
// ---------------------------------------------------------------------------
__global__ __launch_bounds__(256)
void k_scatter(const int* __restrict__ ei, int nE, float* __restrict__ out) {
    int gw   = (int)(((unsigned)blockIdx.x * blockDim.x + threadIdx.x) >> 5);
    int lane = threadIdx.x & 31;
    if (gw >= 2 * nE) return;

    int s, d;
    if (gw < nE) { s = ei[gw];      d = ei[nE + gw]; }
    else         { int e = gw - nE; d = ei[e]; s = ei[nE + e]; }

    float4 v = reinterpret_cast<const float4*>(g_y1 + (size_t)s * H)[lane];
    float4* o = reinterpret_cast<float4*>(out + (size_t)d * H) + lane;
    asm volatile("red.global.add.v4.f32 [%0], {%1, %2, %3, %4};"
                 :: "l"(o), "f"(v.x), "f"(v.y), "f"(v.z), "f"(v.w)
                 : "memory");
}

// ---------------------------------------------------------------------------
extern "C" void kernel_launch(void* const* d_in, const int* in_sizes, int n_in,
                              void* d_out, int out_size) {
    const float* x  = (const float*)d_in[0];   // [NV, 128] f32
    const float* W  = (const float*)d_in[1];   // [128, 256] f32
    const int*   ei = (const int*)d_in[2];     // [2, E] i32
    float* out = (float*)d_out;                // [NV, 128] f32

    int nE    = in_sizes[2] / 2;
    int total = in_sizes[2];

    k_zero_cnt<<<(NV + 255) / 256, 256>>>();
    k_hist<<<(total / 4 + 255) / 256, 256>>>(ei, total);

    dim3 ggrid((NV + 127) / 128, 2);
    k_gemm<<<ggrid, 256>>>(x, W, out);

    k_scatter<<<(2 * nE * 32 + 255) / 256, 256>>>(ei, nE, out);

    (void)n_in; (void)out_size;
}